// round 16
// baseline (speedup 1.0000x reference)
#include <cuda_runtime.h>
#include <cuda_bf16.h>

#define MAXN 100000
#define MAXE 3200000
#define FIN  256
#define FOUT 64

// Scratch (device globals — allocation is forbidden)
__device__ float g_h[MAXN * FOUT];     // projected features (25.6 MB, L2-resident)
__device__ float g_as[MAXN];           // h · att_src
__device__ float g_ad[MAXN];           // h · att_dst
__device__ int   g_cnt[MAXN];          // in-degree (zeroed by scan1 after read)
__device__ int   g_offs[MAXN];         // block-partial exclusive scan (+ cursor)
__device__ int   g_soff[MAXN];         // block-partial exclusive scan (frozen)
__device__ int   g_bsum[512];          // scan block sums (exclusive)
__device__ int   g_src[MAXE];          // dst-sorted source ids
__device__ float g_p[MAXE];            // dst-sorted unnormalized softmax weights

static __device__ __forceinline__ float leaky(float v) {
    return v > 0.0f ? v : 0.2f * v;
}

// ---------------------------------------------------------------------------
// K1: h = x @ W  (SGEMM, BM=128, BN=64, BK=16, 8x4/thread) using packed
//     fma.rn.f32x2 (identical to measured R15 kernel).
//     Fused: in-degree histogram, epilogue a_src/a_dst per row.
// ---------------------------------------------------------------------------
__global__ __launch_bounds__(256) void k_gemm(const float* __restrict__ x,
                                              const float* __restrict__ W,
                                              const float* __restrict__ att_src,
                                              const float* __restrict__ att_dst,
                                              const int* __restrict__ ei,
                                              int n, int e) {
    __shared__ float  AsT[2][16][138];   // [buf][kk][row]
    __shared__ float4 Bs[2][16][16];

    const int tid  = threadIdx.x;
    const int row0 = blockIdx.x * 128;
    const int tcol = tid & 15;
    const int trow = tid >> 4;           // thread owns rows trow*8 .. trow*8+7

    // ---- fused histogram: this block's slice of dst ids (REDs drain async)
    {
        int epb = (e + gridDim.x - 1) / gridDim.x;
        int e0 = blockIdx.x * epb;
        int e1 = min(e0 + epb, e);
        for (int i = e0 + tid; i < e1; i += 256)
            atomicAdd(&g_cnt[__ldg(ei + (size_t)e + i)], 1);
    }

    unsigned long long accP[4][4];
#pragma unroll
    for (int pi = 0; pi < 4; pi++)
#pragma unroll
        for (int j = 0; j < 4; j++) accP[pi][j] = 0ull;

    // ---- prologue: load k-tile 0 into buffer 0
    {
#pragma unroll
        for (int l = 0; l < 2; l++) {
            int idx = tid + l * 256;
            int r = idx >> 2, q = idx & 3;
            float4 v = make_float4(0.f, 0.f, 0.f, 0.f);
            int gr = row0 + r;
            if (gr < n)
                v = *(const float4*)(x + (size_t)gr * FIN + q * 4);
            AsT[0][q * 4 + 0][r] = v.x; AsT[0][q * 4 + 1][r] = v.y;
            AsT[0][q * 4 + 2][r] = v.z; AsT[0][q * 4 + 3][r] = v.w;
        }
        int k = tid >> 4, cq = tid & 15;
        Bs[0][k][cq] = *(const float4*)(W + (size_t)k * FOUT + cq * 4);
    }
    __syncthreads();

    int buf = 0;
    for (int k0 = 0; k0 < FIN; k0 += 16) {
        const bool has_next = (k0 + 16) < FIN;
        float4 pa0, pa1, pbv;
        if (has_next) {
            const int k1 = k0 + 16;
            {
                int r = tid >> 2, q = tid & 3;
                int gr = row0 + r;
                pa0 = (gr < n) ? *(const float4*)(x + (size_t)gr * FIN + k1 + q * 4)
                               : make_float4(0.f, 0.f, 0.f, 0.f);
            }
            {
                int idx = tid + 256;
                int r = idx >> 2, q = idx & 3;
                int gr = row0 + r;
                pa1 = (gr < n) ? *(const float4*)(x + (size_t)gr * FIN + k1 + q * 4)
                               : make_float4(0.f, 0.f, 0.f, 0.f);
            }
            {
                int k = tid >> 4, cq = tid & 15;
                pbv = *(const float4*)(W + (size_t)(k1 + k) * FOUT + cq * 4);
            }
        }

        const int rowbase = trow * 8;
#pragma unroll
        for (int kk = 0; kk < 16; kk++) {
            float4 b = Bs[buf][kk][tcol];
            unsigned long long bb0, bb1, bb2, bb3;
            asm("mov.b64 %0, {%1, %1};" : "=l"(bb0) : "f"(b.x));
            asm("mov.b64 %0, {%1, %1};" : "=l"(bb1) : "f"(b.y));
            asm("mov.b64 %0, {%1, %1};" : "=l"(bb2) : "f"(b.z));
            asm("mov.b64 %0, {%1, %1};" : "=l"(bb3) : "f"(b.w));
#pragma unroll
            for (int pi = 0; pi < 4; pi++) {
                unsigned long long aa =
                    *(const unsigned long long*)&AsT[buf][kk][rowbase + 2 * pi];
                asm("fma.rn.f32x2 %0, %1, %2, %0;" : "+l"(accP[pi][0])
                    : "l"(aa), "l"(bb0));
                asm("fma.rn.f32x2 %0, %1, %2, %0;" : "+l"(accP[pi][1])
                    : "l"(aa), "l"(bb1));
                asm("fma.rn.f32x2 %0, %1, %2, %0;" : "+l"(accP[pi][2])
                    : "l"(aa), "l"(bb2));
                asm("fma.rn.f32x2 %0, %1, %2, %0;" : "+l"(accP[pi][3])
                    : "l"(aa), "l"(bb3));
            }
        }

        if (has_next) {
            int nb = buf ^ 1;
            {
                int r = tid >> 2, q = tid & 3;
                AsT[nb][q * 4 + 0][r] = pa0.x; AsT[nb][q * 4 + 1][r] = pa0.y;
                AsT[nb][q * 4 + 2][r] = pa0.z; AsT[nb][q * 4 + 3][r] = pa0.w;
            }
            {
                int idx = tid + 256;
                int r = idx >> 2, q = idx & 3;
                AsT[nb][q * 4 + 0][r] = pa1.x; AsT[nb][q * 4 + 1][r] = pa1.y;
                AsT[nb][q * 4 + 2][r] = pa1.z; AsT[nb][q * 4 + 3][r] = pa1.w;
            }
            {
                int k = tid >> 4, cq = tid & 15;
                Bs[nb][k][cq] = pbv;
            }
            __syncthreads();
            buf = nb;
        }
    }

    float acc[8][4];
#pragma unroll
    for (int pi = 0; pi < 4; pi++)
#pragma unroll
        for (int j = 0; j < 4; j++) {
            float lo, hi;
            asm("mov.b64 {%0, %1}, %2;" : "=f"(lo), "=f"(hi) : "l"(accP[pi][j]));
            acc[2 * pi][j]     = lo;
            acc[2 * pi + 1][j] = hi;
        }

    const float4 asv = *(const float4*)(att_src + tcol * 4);
    const float4 adv = *(const float4*)(att_dst + tcol * 4);

#pragma unroll
    for (int i = 0; i < 8; i++) {
        int r = row0 + trow * 8 + i;
        float sa = acc[i][0] * asv.x + acc[i][1] * asv.y
                 + acc[i][2] * asv.z + acc[i][3] * asv.w;
        float sd = acc[i][0] * adv.x + acc[i][1] * adv.y
                 + acc[i][2] * adv.z + acc[i][3] * adv.w;
#pragma unroll
        for (int o = 8; o > 0; o >>= 1) {
            sa += __shfl_xor_sync(0xFFFFFFFFu, sa, o);
            sd += __shfl_xor_sync(0xFFFFFFFFu, sd, o);
        }
        if (r < n) {
            *(float4*)(g_h + (size_t)r * FOUT + tcol * 4) =
                make_float4(acc[i][0], acc[i][1], acc[i][2], acc[i][3]);
            if (tcol == 0) {
                g_as[r] = sa;
                g_ad[r] = sd;
            }
        }
    }
}

// ---------------------------------------------------------------------------
// K2a: block-partial exclusive scan of cnt -> offs + soff; zeroes cnt
//      (consumers add g_bsum[i>>8] for the final prefix)
// ---------------------------------------------------------------------------
__global__ __launch_bounds__(256) void k_scan1(int n) {
    __shared__ int sh[256];
    int i = blockIdx.x * 256 + threadIdx.x;
    int v = (i < n) ? g_cnt[i] : 0;
    sh[threadIdx.x] = v;
    __syncthreads();
#pragma unroll
    for (int o = 1; o < 256; o <<= 1) {
        int t = (threadIdx.x >= o) ? sh[threadIdx.x - o] : 0;
        __syncthreads();
        sh[threadIdx.x] += t;
        __syncthreads();
    }
    if (i < n) {
        int ex = sh[threadIdx.x] - v;   // block-partial exclusive
        g_offs[i] = ex;                 // atomic cursor (scatter advances it)
        g_soff[i] = ex;                 // frozen copy (agg reads start)
        g_cnt[i]  = 0;                  // ready for next replay's histogram
    }
    if (threadIdx.x == 255) g_bsum[blockIdx.x] = sh[255];
}

// K2b: exclusive scan of block sums
__global__ __launch_bounds__(512) void k_scan2(int nb) {
    __shared__ int sh[512];
    int t = threadIdx.x;
    int v = (t < nb) ? g_bsum[t] : 0;
    sh[t] = v;
    __syncthreads();
#pragma unroll
    for (int o = 1; o < 512; o <<= 1) {
        int u = (t >= o) ? sh[t - o] : 0;
        __syncthreads();
        sh[t] += u;
        __syncthreads();
    }
    if (t < nb) g_bsum[t] = sh[t] - v;                  // exclusive
}

// ---------------------------------------------------------------------------
// K3: scatter — dst-sorted (src, p); final slot = partial cursor + bsum[blk].
// ---------------------------------------------------------------------------
__global__ __launch_bounds__(256) void k_scatter(const int* __restrict__ ei, int e) {
    int i = blockIdx.x * 256 + threadIdx.x;
    if (i >= e) return;
    int s = __ldg(ei + i);
    int d = __ldg(ei + e + i);
    float p = __expf(leaky(__ldg(&g_as[s]) + __ldg(&g_ad[d])));
    int pos = atomicAdd(&g_offs[d], 1) + __ldg(&g_bsum[d >> 8]);
    g_src[pos] = s;
    g_p[pos]   = p;
}

// ---------------------------------------------------------------------------
// K4: warp-per-dst aggregation, 4 edges in flight per warp (2 subgroups x
//     unroll 2). start/end from soff/offs + bsum. Epilogue: self-loop +
//     normalize + bias; single store.
// ---------------------------------------------------------------------------
__global__ __launch_bounds__(256) void k_agg(const float* __restrict__ bias,
                                             float* __restrict__ out, int n) {
    int node = (int)((blockIdx.x * 256u + threadIdx.x) >> 5);
    if (node >= n) return;
    int lane = threadIdx.x & 31;
    int sub  = lane & 15;
    int half = lane >> 4;               // 0 or 1

    int bs    = g_bsum[node >> 8];
    int start = g_soff[node] + bs;      // frozen exclusive prefix
    int end   = g_offs[node] + bs;      // cursor after scatter = prefix + deg

    float4 acc = make_float4(0.f, 0.f, 0.f, 0.f);
    float denl = 0.0f;

    int base = start;
    for (; base + 4 <= end; base += 4) {
        int i0 = base + half;
        int i1 = i0 + 2;
        int   s0 = __ldg(&g_src[i0]);
        int   s1 = __ldg(&g_src[i1]);
        float p0 = __ldg(&g_p[i0]);
        float p1 = __ldg(&g_p[i1]);
        const float4 h0 = *(const float4*)(g_h + (size_t)s0 * FOUT + sub * 4);
        const float4 h1 = *(const float4*)(g_h + (size_t)s1 * FOUT + sub * 4);
        acc.x += p0 * h0.x + p1 * h1.x;
        acc.y += p0 * h0.y + p1 * h1.y;
        acc.z += p0 * h0.z + p1 * h1.z;
        acc.w += p0 * h0.w + p1 * h1.w;
        if (sub == 0) denl += p0 + p1;
    }
    for (; base < end; base += 2) {
        int i0 = base + half;
        if (i0 < end) {
            int   s0 = __ldg(&g_src[i0]);
            float p0 = __ldg(&g_p[i0]);
            const float4 h0 = *(const float4*)(g_h + (size_t)s0 * FOUT + sub * 4);
            acc.x += p0 * h0.x;
            acc.y += p0 * h0.y;
            acc.z += p0 * h0.z;
            acc.w += p0 * h0.w;
            if (sub == 0) denl += p0;
        }
    }

    // combine the two 16-lane subgroups
    acc.x += __shfl_xor_sync(0xFFFFFFFFu, acc.x, 16);
    acc.y += __shfl_xor_sync(0xFFFFFFFFu, acc.y, 16);
    acc.z += __shfl_xor_sync(0xFFFFFFFFu, acc.z, 16);
    acc.w += __shfl_xor_sync(0xFFFFFFFFu, acc.w, 16);
    float den = __shfl_sync(0xFFFFFFFFu, denl, 0)
              + __shfl_sync(0xFFFFFFFFu, denl, 16);

    float ps  = __expf(leaky(g_as[node] + g_ad[node]));   // self-loop weight
    float inv = 1.0f / (den + ps + 1e-16f);

    if (lane < 16) {
        const float4 hi4 = *(const float4*)(g_h + (size_t)node * FOUT + sub * 4);
        const float4 b4  = *(const float4*)(bias + sub * 4);
        float4 o;
        o.x = (acc.x + ps * hi4.x) * inv + b4.x;
        o.y = (acc.y + ps * hi4.y) * inv + b4.y;
        o.z = (acc.z + ps * hi4.z) * inv + b4.z;
        o.w = (acc.w + ps * hi4.w) * inv + b4.w;
        *(float4*)(out + (size_t)node * FOUT + sub * 4) = o;
    }
}

// ---------------------------------------------------------------------------
extern "C" void kernel_launch(void* const* d_in, const int* in_sizes, int n_in,
                              void* d_out, int out_size) {
    const float* x       = (const float*)d_in[0];
    const int*   ei      = (const int*)d_in[1];
    const float* W       = (const float*)d_in[2];
    const float* att_src = (const float*)d_in[3];
    const float* att_dst = (const float*)d_in[4];
    const float* bias    = (const float*)d_in[5];
    float* out = (float*)d_out;

    const int n = in_sizes[0] / FIN;   // 100000
    const int e = in_sizes[1] / 2;     // 3200000
    const int nb = (n + 255) / 256;    // scan blocks (391 <= 512)

    // K1: projection (f32x2-packed) + attention halves + fused histogram
    k_gemm<<<(n + 127) / 128, 256>>>(x, W, att_src, att_dst, ei, n, e);
    // K2: partial scan (+cnt reset) and block-sum scan
    k_scan1<<<nb, 256>>>(n);
    k_scan2<<<1, 512>>>(nb);
    // K3: dst-sorted scatter of (src, p)
    k_scatter<<<(e + 255) / 256, 256>>>(ei, e);
    // K4: warp-per-dst aggregation (+softmax normalize, self-loop, bias)
    k_agg<<<(n + 7) / 8, 256>>>(bias, out, n);
}